// round 11
// baseline (speedup 1.0000x reference)
#include <cuda_runtime.h>
#include <cuda_fp16.h>
#include <cstdint>

#define N_HEADS 4
#define H_DIM   128
#define TOK_F   512
#define K_DIM   4096
#define BLK     32
#define STRIDE  16
#define MAXSEQ  256

#define NSTEPS  64
#define KT      64              // K halves per step
#define A_BYTES 8192            // 64 rows x 128B
#define B_BYTES 16384           // 128 rows x 128B
#define SMEM_GEMM (2 * A_BYTES + 4 * B_BYTES + 128)

// ---------------- device scratch ----------------
__device__ int    g_bases[65536];
__device__ int    g_total_out;
__device__ __half g_wT[2][(size_t)K_DIM * H_DIM];   // [mat][n*4096 + k] = w[k*128+n]

static __device__ __forceinline__ uint32_t smem_u32(const void* p) {
    uint32_t a;
    asm("{ .reg .u64 t; cvta.to.shared.u64 t, %1; cvt.u32.u64 %0, t; }" : "=r"(a) : "l"(p));
    return a;
}

// K-order permutation: step s -> j index (interleave j and j+16 so the
// stride-16 block overlap becomes L2-resident between uses).
static __device__ __forceinline__ int j_of(int s) {
    int jj = s >> 1;
    return (jj >> 1) + ((jj & 1) << 4);      // 0,16,1,17,...,15,31
}
static __device__ __forceinline__ int a_off(int s) {    // float offset into token row
    return j_of(s) * TOK_F + (s & 1) * KT;
}
static __device__ __forceinline__ int k_off(int s) {    // half offset into wT row
    return j_of(s) * 128 + (s & 1) * KT;
}

#define CP_ASYNC16(dst, src) \
    asm volatile("cp.async.cg.shared.global [%0], [%1], 16;" :: "r"(dst), "l"(src) : "memory")
#define CP_COMMIT()  asm volatile("cp.async.commit_group;" ::: "memory")
#define CP_WAITALL() asm volatile("cp.async.wait_all;" ::: "memory")

#define BAR_HALF(id) \
    asm volatile("bar.sync %0, 128;" :: "r"(id) : "memory")

#define LDMATRIX_X4(r0, r1, r2, r3, addr) \
    asm volatile("ldmatrix.sync.aligned.m8n8.x4.shared.b16 {%0,%1,%2,%3}, [%4];" \
                 : "=r"(r0), "=r"(r1), "=r"(r2), "=r"(r3) : "r"(addr))

// fp16-accumulate MMA: D,C packed half2 x2
#define MMAF16(c, a0, a1, a2, a3, b0, b1) \
    asm volatile("mma.sync.aligned.m16n8k16.row.col.f16.f16.f16.f16 " \
                 "{%0,%1}, {%2,%3,%4,%5}, {%6,%7}, {%0,%1};" \
                 : "+r"((c)[0]), "+r"((c)[1]) \
                 : "r"(a0), "r"(a1), "r"(a2), "r"(a3), "r"(b0), "r"(b1))

// ---------------- kernel 1: prep = ragged metadata + W transpose/convert ----------------
__global__ void prep_kernel(const int* __restrict__ cu, int nseq,
                            const float* __restrict__ wk, const float* __restrict__ wv,
                            float* __restrict__ dout) {
    if (blockIdx.x == 1024) {
        __shared__ int s_ol[MAXSEQ];
        __shared__ int s_cu[MAXSEQ + 1];
        int t = threadIdx.y * 32 + threadIdx.x;
        if (t < nseq) {
            int n = cu[t + 1] - cu[t];
            s_ol[t] = (n >= BLK) ? (n - BLK) / STRIDE : 0;
        }
        __syncthreads();
        if (t == 0) {
            int acc = 0;
            s_cu[0] = 0;
            for (int b = 0; b < nseq; b++) { acc += s_ol[b]; s_cu[b + 1] = acc; }
            g_total_out = acc;
        }
        __syncthreads();
        int total = s_cu[nseq];
        for (int i = t; i <= nseq; i += 256)
            dout[(size_t)2 * total * 512 + i] = (float)s_cu[i];
        for (int o = t; o < total; o += 256) {
            int b = 0;
            while (s_cu[b + 1] <= o) b++;
            g_bases[o] = cu[b] + (o - s_cu[b]) * STRIDE;
        }
        return;
    }
    __shared__ float tile[32][33];
    int bx = blockIdx.x;
    int z   = bx >> 9;
    int rem = bx & 511;
    int kb  = rem & 127;
    int nb  = rem >> 7;
    const float* w = z ? wv : wk;
    __half* out = g_wT[z];
    int k0 = kb * 32, n0 = nb * 32;
    int tx = threadIdx.x, ty = threadIdx.y;   // (32, 8)
#pragma unroll
    for (int i = 0; i < 32; i += 8)
        tile[ty + i][tx] = w[(size_t)(k0 + ty + i) * H_DIM + n0 + tx];
    __syncthreads();
#pragma unroll
    for (int i = 0; i < 32; i += 8)
        out[(size_t)(n0 + ty + i) * K_DIM + k0 + tx] = __float2half_rn(tile[tx][ty + i]);
}

// store 4 float4 (32 fp32) as 2 swizzled uint4 rows of fp16
static __device__ __forceinline__ void cvt_store_A(char* smem, uint32_t ast0, uint32_t ast1,
                                                   const float4* rv) {
    __half2 h;
    uint4 s0, s1;
    h = __floats2half2_rn(rv[0].x, rv[0].y); s0.x = *(uint32_t*)&h;
    h = __floats2half2_rn(rv[0].z, rv[0].w); s0.y = *(uint32_t*)&h;
    h = __floats2half2_rn(rv[1].x, rv[1].y); s0.z = *(uint32_t*)&h;
    h = __floats2half2_rn(rv[1].z, rv[1].w); s0.w = *(uint32_t*)&h;
    h = __floats2half2_rn(rv[2].x, rv[2].y); s1.x = *(uint32_t*)&h;
    h = __floats2half2_rn(rv[2].z, rv[2].w); s1.y = *(uint32_t*)&h;
    h = __floats2half2_rn(rv[3].x, rv[3].y); s1.z = *(uint32_t*)&h;
    h = __floats2half2_rn(rv[3].z, rv[3].w); s1.w = *(uint32_t*)&h;
    *(uint4*)(smem + ast0) = s0;
    *(uint4*)(smem + ast1) = s1;
}

// ---------------- kernel 2: HMMA GEMM ----------------
// 256 thr = 8 warps in 2(M) x 4(N); warp tile 32x32; CTA tile 64x128; K-step 64.
// 2 CTAs/SM. R9 sync scheme; K order permuted (j, j+16 interleave) so the
// stride-16 token overlap is L2-resident between its two uses.
__global__ __launch_bounds__(256, 2)
void gemm_kernel(const float* __restrict__ kin, const float* __restrict__ vin,
                 float* __restrict__ dout) {
    extern __shared__ __align__(128) char smem[];
    const uint32_t sa = smem_u32(smem);            // A: 2 x 8KB
    const uint32_t sb = sa + 2 * A_BYTES;          // B: 4 x 16KB
    int* s_base = (int*)(smem + 2 * A_BYTES + 4 * B_BYTES);

    const int tid = threadIdx.x;
    const int wid = tid >> 5;
    const int lid = tid & 31;
    const int total_out = g_total_out;
    const int o0 = blockIdx.x * 16;               // 16 output blocks (64 rows) per CTA
    if (o0 >= total_out) return;

    const int mat = blockIdx.y;
    const float* __restrict__ x = mat ? vin : kin;
    const __half* __restrict__ wT = g_wT[mat];
    float* __restrict__ outp = dout + (size_t)mat * (size_t)total_out * 512;

    if (tid < 16) {
        int o = o0 + tid;
        if (o >= total_out) o = total_out - 1;
        s_base[tid] = g_bases[o];
    }
    __syncthreads();

    // ---- A writer: half h = tid>>7 owns rows h*32..+31 (matches reader half wr) ----
    const int ht    = tid & 127;
    const int m_row = (tid >> 7) * 32 + (ht >> 2);
    const int q     = tid & 3;
    const float* aptr = x + (size_t)s_base[m_row >> 2] * TOK_F
                          + (size_t)(m_row & 3) * H_DIM + q * 16;
    const uint32_t ast0 = (uint32_t)(m_row * 128 + (((2 * q)     ^ (m_row & 7)) * 16));
    const uint32_t ast1 = (uint32_t)(m_row * 128 + (((2 * q + 1) ^ (m_row & 7)) * 16));

    // ---- B cp.async: thread handles n = tid>>1, chunks (tid&1)*4 + i ----
    const __half* bsrc0;
    uint32_t bdst[4];
    {
        int n = tid >> 1, c0 = (tid & 1) * 4;
        bsrc0 = wT + (size_t)n * K_DIM + c0 * 8;
#pragma unroll
        for (int i = 0; i < 4; i++)
            bdst[i] = sb + (uint32_t)(n * 128 + (((c0 + i) ^ (n & 7)) * 16));
    }

    // ---- ldmatrix addresses ----
    const int wr = wid >> 2;       // M position 0..1
    const int wc = wid & 3;        // N position 0..3
    const int g  = lid >> 3;       // tile group 0..3
    const int l7 = lid & 7;
    uint32_t lma[2][4];
#pragma unroll
    for (int ma = 0; ma < 2; ma++) {
        int r = wr * 32 + ma * 16 + (g & 1) * 8 + l7;
#pragma unroll
        for (int k16i = 0; k16i < 4; k16i++) {
            int c = (2 * k16i + (g >> 1)) ^ (r & 7);
            lma[ma][k16i] = sa + (uint32_t)(r * 128 + c * 16);
        }
    }
    uint32_t lmb[2][4];
#pragma unroll
    for (int p = 0; p < 2; p++) {
        int n = wc * 32 + (2 * p + (g >> 1)) * 8 + l7;
#pragma unroll
        for (int k16i = 0; k16i < 4; k16i++) {
            int c = (2 * k16i + (g & 1)) ^ (n & 7);
            lmb[p][k16i] = sb + (uint32_t)(n * 128 + c * 16);
        }
    }

    float acc[2][4][4];          // fp32 master accumulators
    uint32_t facc[2][4][2];      // fp16 window accumulators
#pragma unroll
    for (int ma = 0; ma < 2; ma++)
#pragma unroll
        for (int na = 0; na < 4; na++) {
#pragma unroll
            for (int e = 0; e < 4; e++) acc[ma][na][e] = 0.f;
            facc[ma][na][0] = 0u; facc[ma][na][1] = 0u;
        }

    // ---- prologue: B steps 0,1; A step 0 -> slot 0 (j_of(0)=0, j_of(1)=0) ----
#pragma unroll
    for (int i = 0; i < 4; i++) CP_ASYNC16(bdst[i], bsrc0 + k_off(0) + i * 8);
    CP_COMMIT();
#pragma unroll
    for (int i = 0; i < 4; i++) CP_ASYNC16(bdst[i] + B_BYTES, bsrc0 + k_off(1) + i * 8);
    CP_COMMIT();
    {
        float4 rv[4];
#pragma unroll
        for (int i = 0; i < 4; i++) rv[i] = *(const float4*)(aptr + a_off(0) + 4 * i);
        cvt_store_A(smem, ast0, ast1, rv);
    }

#pragma unroll 1
    for (int s = 0; s < NSTEPS; s += 2) {
        // retire ALL outstanding B groups (for steps s, s+1), then CTA-wide publish.
        CP_WAITALL();
        __syncthreads();

        // issue B for steps s+2, s+3 into slots (s+2)&3, (s+3)&3.
        if (s + 2 < NSTEPS) {
            const int koff = k_off(s + 2);
#pragma unroll
            for (int i = 0; i < 4; i++)
                CP_ASYNC16(bdst[i] + ((s + 2) & 3) * B_BYTES, bsrc0 + koff + i * 8);
            CP_COMMIT();
        }
        if (s + 3 < NSTEPS) {
            const int koff = k_off(s + 3);
#pragma unroll
            for (int i = 0; i < 4; i++)
                CP_ASYNC16(bdst[i] + ((s + 3) & 3) * B_BYTES, bsrc0 + koff + i * 8);
            CP_COMMIT();
        }

        // ======== step s (even): A slot 0, B slot s&3 ========
        float4 rv[4];
        {   // prefetch A(s+1)
            const int aoff = a_off(s + 1);
#pragma unroll
            for (int i = 0; i < 4; i++) rv[i] = *(const float4*)(aptr + aoff + 4 * i);
        }
        {
            const uint32_t bbuf = (uint32_t)((s & 3) * B_BYTES);
#pragma unroll
            for (int k16i = 0; k16i < 4; k16i++) {
                uint32_t a0[4], a1[4], b0[4], b1[4];
                LDMATRIX_X4(a0[0], a0[1], a0[2], a0[3], lma[0][k16i]);
                LDMATRIX_X4(a1[0], a1[1], a1[2], a1[3], lma[1][k16i]);
                LDMATRIX_X4(b0[0], b0[1], b0[2], b0[3], lmb[0][k16i] + bbuf);
                LDMATRIX_X4(b1[0], b1[1], b1[2], b1[3], lmb[1][k16i] + bbuf);
                MMAF16(facc[0][0], a0[0], a0[1], a0[2], a0[3], b0[0], b0[1]);
                MMAF16(facc[0][1], a0[0], a0[1], a0[2], a0[3], b0[2], b0[3]);
                MMAF16(facc[0][2], a0[0], a0[1], a0[2], a0[3], b1[0], b1[1]);
                MMAF16(facc[0][3], a0[0], a0[1], a0[2], a0[3], b1[2], b1[3]);
                MMAF16(facc[1][0], a1[0], a1[1], a1[2], a1[3], b0[0], b0[1]);
                MMAF16(facc[1][1], a1[0], a1[1], a1[2], a1[3], b0[2], b0[3]);
                MMAF16(facc[1][2], a1[0], a1[1], a1[2], a1[3], b1[0], b1[1]);
                MMAF16(facc[1][3], a1[0], a1[1], a1[2], a1[3], b1[2], b1[3]);
            }
        }
        // store A(s+1) -> slot 1
        cvt_store_A(smem + A_BYTES, ast0, ast1, rv);
        BAR_HALF(1 + wr);   // publish A slot 1 within this half

        // ======== step s+1 (odd): A slot 1, B slot (s+1)&3 ========
        const bool pf2 = (s + 2 < NSTEPS);
        if (pf2) {
            const int aoff = a_off(s + 2);
#pragma unroll
            for (int i = 0; i < 4; i++) rv[i] = *(const float4*)(aptr + aoff + 4 * i);
        }
        {
            const uint32_t bbuf = (uint32_t)(((s + 1) & 3) * B_BYTES);
#pragma unroll
            for (int k16i = 0; k16i < 4; k16i++) {
                uint32_t a0[4], a1[4], b0[4], b1[4];
                LDMATRIX_X4(a0[0], a0[1], a0[2], a0[3], lma[0][k16i] + A_BYTES);
                LDMATRIX_X4(a1[0], a1[1], a1[2], a1[3], lma[1][k16i] + A_BYTES);
                LDMATRIX_X4(b0[0], b0[1], b0[2], b0[3], lmb[0][k16i] + bbuf);
                LDMATRIX_X4(b1[0], b1[1], b1[2], b1[3], lmb[1][k16i] + bbuf);
                MMAF16(facc[0][0], a0[0], a0[1], a0[2], a0[3], b0[0], b0[1]);
                MMAF16(facc[0][1], a0[0], a0[1], a0[2], a0[3], b0[2], b0[3]);
                MMAF16(facc[0][2], a0[0], a0[1], a0[2], a0[3], b1[0], b1[1]);
                MMAF16(facc[0][3], a0[0], a0[1], a0[2], a0[3], b1[2], b1[3]);
                MMAF16(facc[1][0], a1[0], a1[1], a1[2], a1[3], b0[0], b0[1]);
                MMAF16(facc[1][1], a1[0], a1[1], a1[2], a1[3], b0[2], b0[3]);
                MMAF16(facc[1][2], a1[0], a1[1], a1[2], a1[3], b1[0], b1[1]);
                MMAF16(facc[1][3], a1[0], a1[1], a1[2], a1[3], b1[2], b1[3]);
            }
        }
        // flush fp16 window into fp32 (window = steps s, s+1)
#pragma unroll
        for (int ma = 0; ma < 2; ma++)
#pragma unroll
            for (int na = 0; na < 4; na++) {
                float2 f0 = __half22float2(*reinterpret_cast<__half2*>(&facc[ma][na][0]));
                float2 f1 = __half22float2(*reinterpret_cast<__half2*>(&facc[ma][na][1]));
                acc[ma][na][0] += f0.x; acc[ma][na][1] += f0.y;
                acc[ma][na][2] += f1.x; acc[ma][na][3] += f1.y;
                facc[ma][na][0] = 0u; facc[ma][na][1] = 0u;
            }
        // store A(s+2) -> slot 0
        if (pf2) cvt_store_A(smem, ast0, ast1, rv);
    }

    // ---- epilogue ----
    const int Rmax = total_out * 4;
    const int l4 = lid >> 2, lc = lid & 3;
#pragma unroll
    for (int ma = 0; ma < 2; ma++) {
        int R0 = o0 * 4 + wr * 32 + ma * 16 + l4;
#pragma unroll
        for (int na = 0; na < 4; na++) {
            int col = wc * 32 + na * 8 + lc * 2;
            if (R0 < Rmax)
                *(float2*)(outp + (size_t)R0 * 128 + col) =
                    make_float2(acc[ma][na][0], acc[ma][na][1]);
            if (R0 + 8 < Rmax)
                *(float2*)(outp + (size_t)(R0 + 8) * 128 + col) =
                    make_float2(acc[ma][na][2], acc[ma][na][3]);
        }
    }
}

// ---------------- launch ----------------
extern "C" void kernel_launch(void* const* d_in, const int* in_sizes, int n_in,
                              void* d_out, int out_size) {
    const float* k  = (const float*)d_in[0];
    const float* v  = (const float*)d_in[1];
    const float* wk = (const float*)d_in[2];
    const float* wv = (const float*)d_in[3];
    const int*   cu = (const int*)d_in[4];
    int nseq = in_sizes[4] - 1;
    int total_tokens = in_sizes[0] / (N_HEADS * H_DIM);

    prep_kernel<<<1025, dim3(32, 8)>>>(cu, nseq, wk, wv, (float*)d_out);

    int max_out = total_tokens / STRIDE;
    int ntiles = (max_out + 15) / 16;
    cudaFuncSetAttribute(gemm_kernel, cudaFuncAttributeMaxDynamicSharedMemorySize, SMEM_GEMM);
    gemm_kernel<<<dim3(ntiles, 2), 256, SMEM_GEMM>>>(k, v, (float*)d_out);
}

// round 12
// speedup vs baseline: 1.5549x; 1.5549x over previous
#include <cuda_runtime.h>
#include <cuda_fp16.h>
#include <cstdint>

#define N_HEADS 4
#define H_DIM   128
#define TOK_F   512
#define K_DIM   4096
#define BLK     32
#define STRIDE  16
#define MAXSEQ  256
#define MAXTILE 8192

#define NSUB    64              // 64 substeps of K=64 (16 supersteps x 4)
#define KT      64
#define A_SLOT  17408           // 2(dh) x 68 rows x 128B
#define B_BYTES 16384           // 128 n-rows x 64 halves
#define SB_OFF  (2 * A_SLOT)
#define TOK_OFF (2 * A_SLOT + 4 * B_BYTES)
#define SMEM_GEMM (TOK_OFF + 128)

// ---------------- device scratch ----------------
__device__ int    g_total_out;
__device__ int    g_ntiles;
__device__ int    g_tile_o0[MAXTILE];
__device__ int    g_tile_tok0[MAXTILE];
__device__ int    g_tile_lim[MAXTILE];
__device__ int    g_tile_nrow[MAXTILE];
__device__ __half g_wT[2][(size_t)K_DIM * H_DIM];   // [mat][n*4096 + k] = w[k*128+n]

static __device__ __forceinline__ uint32_t smem_u32(const void* p) {
    uint32_t a;
    asm("{ .reg .u64 t; cvta.to.shared.u64 t, %1; cvt.u32.u64 %0, t; }" : "=r"(a) : "l"(p));
    return a;
}

#define CP_ASYNC16(dst, src) \
    asm volatile("cp.async.cg.shared.global [%0], [%1], 16;" :: "r"(dst), "l"(src) : "memory")
#define CP_COMMIT()  asm volatile("cp.async.commit_group;" ::: "memory")
#define CP_WAITALL() asm volatile("cp.async.wait_all;" ::: "memory")

#define LDMATRIX_X4(r0, r1, r2, r3, addr) \
    asm volatile("ldmatrix.sync.aligned.m8n8.x4.shared.b16 {%0,%1,%2,%3}, [%4];" \
                 : "=r"(r0), "=r"(r1), "=r"(r2), "=r"(r3) : "r"(addr))

// fp16-accumulate MMA: D,C packed half2 x2
#define MMAF16(c, a0, a1, a2, a3, b0, b1) \
    asm volatile("mma.sync.aligned.m16n8k16.row.col.f16.f16.f16.f16 " \
                 "{%0,%1}, {%2,%3,%4,%5}, {%6,%7}, {%0,%1};" \
                 : "+r"((c)[0]), "+r"((c)[1]) \
                 : "r"(a0), "r"(a1), "r"(a2), "r"(a3), "r"(b0), "r"(b1))

// substep u -> k offset (halves) into wT row: j = T + 16*(sub>>1), dhalf = sub&1
static __device__ __forceinline__ int koff_of(int u) {
    int T = u >> 2, sub = u & 3;
    return (T + ((sub & 2) << 3)) * 128 + (sub & 1) * 64;
}

// ---------------- kernel 1: prep = metadata/tile-table + W transpose/convert ----------------
__global__ void prep_kernel(const int* __restrict__ cu, int nseq,
                            const float* __restrict__ wk, const float* __restrict__ wv,
                            float* __restrict__ dout) {
    if (blockIdx.x == 1024) {
        __shared__ int s_ol[MAXSEQ];
        __shared__ int s_cu[MAXSEQ + 1];
        __shared__ int s_ts[MAXSEQ + 1];   // tile prefix
        int t = threadIdx.y * 32 + threadIdx.x;
        if (t < nseq) {
            int n = cu[t + 1] - cu[t];
            s_ol[t] = (n >= BLK) ? (n - BLK) / STRIDE : 0;
        }
        __syncthreads();
        if (t == 0) {
            int acc = 0, tacc = 0;
            s_cu[0] = 0; s_ts[0] = 0;
            for (int b = 0; b < nseq; b++) {
                acc += s_ol[b];
                tacc += (s_ol[b] + 15) >> 4;
                s_cu[b + 1] = acc;
                s_ts[b + 1] = tacc;
            }
            g_total_out = acc;
            g_ntiles = tacc;
        }
        __syncthreads();
        int total = s_cu[nseq];
        int ntl = s_ts[nseq];
        for (int i = t; i <= nseq; i += 256)
            dout[(size_t)2 * total * 512 + i] = (float)s_cu[i];
        for (int x = t; x < ntl; x += 256) {
            int b = 0;
            while (s_ts[b + 1] <= x) b++;
            int ti = x - s_ts[b];
            int o0 = s_cu[b] + ti * 16;
            int ol = s_cu[b + 1] - o0;        // remaining blocks in seq
            g_tile_o0[x]   = o0;
            g_tile_tok0[x] = cu[b] + ti * 256;
            g_tile_lim[x]  = cu[b + 1] - 16;
            g_tile_nrow[x] = (ol < 16 ? ol : 16) * 4;
        }
        return;
    }
    __shared__ float tile[32][33];
    int bx = blockIdx.x;
    int z   = bx >> 9;
    int rem = bx & 511;
    int kb  = rem & 127;
    int nb  = rem >> 7;
    const float* w = z ? wv : wk;
    __half* out = g_wT[z];
    int k0 = kb * 32, n0 = nb * 32;
    int tx = threadIdx.x, ty = threadIdx.y;   // (32, 8)
#pragma unroll
    for (int i = 0; i < 32; i += 8)
        tile[ty + i][tx] = w[(size_t)(k0 + ty + i) * H_DIM + n0 + tx];
    __syncthreads();
#pragma unroll
    for (int i = 0; i < 32; i += 8)
        out[(size_t)(n0 + ty + i) * K_DIM + k0 + tx] = __float2half_rn(tile[tx][ty + i]);
}

// ---------------- kernel 2: HMMA GEMM with token-dedup A staging ----------------
// 256 thr = 8 warps in 2(M) x 4(N); warp tile 32x32; CTA tile 64x128.
// Superstep j stages 17 tokens (fp16); serves k-blocks j AND j+16 (4 K-64 substeps).
// B: 4-slot cp.async rotation, barrier every 2 substeps (R9 proven scheme).
__global__ __launch_bounds__(256, 2)
void gemm_kernel(const float* __restrict__ kin, const float* __restrict__ vin,
                 float* __restrict__ dout) {
    extern __shared__ __align__(128) char smem[];
    const uint32_t sa = smem_u32(smem);            // A: 2 slots x 17408
    const uint32_t sb = sa + SB_OFF;               // B: 4 x 16KB
    int* s_tok = (int*)(smem + TOK_OFF);

    const int tid = threadIdx.x;
    const int wid = tid >> 5;
    const int lid = tid & 31;
    const int bx  = blockIdx.x;
    if (bx >= g_ntiles) return;
    const int total_out = g_total_out;
    const int o0   = g_tile_o0[bx];
    const int tok0 = g_tile_tok0[bx];
    const int lim  = g_tile_lim[bx];
    const int nrow = g_tile_nrow[bx];

    const int mat = blockIdx.y;
    const float* __restrict__ x = mat ? vin : kin;
    const __half* __restrict__ wT = g_wT[mat];
    float* __restrict__ outp = dout + (size_t)mat * (size_t)total_out * 512;

    if (tid < 17) {
        int tk = tok0 + 16 * tid;
        s_tok[tid] = tk < lim ? tk : lim;
    }
    __syncthreads();

    // ---- A staging tasks: tau = sr*8 + dh*4 + cpair; sr=0..67 (slot*4+head) ----
    // thread owns tau = tid, tid+256, tid+512 (last iff tid<32)
    int   sgoff[3];
    uint32_t sadr[3];
    const int ntask3 = (tid < 32) ? 1 : 0;
#pragma unroll
    for (int tsk = 0; tsk < 3; tsk++) {
        int tau = tsk * 256 + tid;
        if (tau >= 544) tau = 543;
        int sr = tau >> 3, dh = (tau >> 2) & 1, cp = tau & 3;
        int i = sr >> 2, h = sr & 3;
        sgoff[tsk] = s_tok[i] * TOK_F + h * H_DIM + dh * 64 + cp * 16;
        sadr[tsk]  = (uint32_t)(dh * 8704 + sr * 128 + (((2 * cp) ^ (sr & 7)) * 16));
    }

    // ---- B cp.async: thread handles n = tid>>1, chunks (tid&1)*4 + i ----
    const __half* bsrc0;
    uint32_t bdst[4];
    {
        int n = tid >> 1, c0 = (tid & 1) * 4;
        bsrc0 = wT + (size_t)n * K_DIM + c0 * 8;
#pragma unroll
        for (int i = 0; i < 4; i++)
            bdst[i] = sb + (uint32_t)(n * 128 + (((c0 + i) ^ (n & 7)) * 16));
    }

    // ---- ldmatrix addresses ----
    const int wr = wid >> 2;       // M position 0..1
    const int wc = wid & 3;        // N position 0..3
    const int g  = lid >> 3;       // tile group 0..3
    const int l7 = lid & 7;
    uint32_t lma[2][4];            // dh=0, hi=0 base addresses (rel to A slot)
    int hidelta[4];                // j+16: rows +4 -> +512 +/- 64
#pragma unroll
    for (int k16i = 0; k16i < 4; k16i++) {
        int c = 2 * k16i + (g >> 1);
        hidelta[k16i] = 512 + (((c ^ l7) & 4) ? -64 : 64);
#pragma unroll
        for (int ma = 0; ma < 2; ma++) {
            int sr = wr * 32 + ma * 16 + (g & 1) * 8 + l7;
            lma[ma][k16i] = sa + (uint32_t)(sr * 128 + ((c ^ (sr & 7)) * 16));
        }
    }
    uint32_t lmb[2][4];
#pragma unroll
    for (int p = 0; p < 2; p++) {
        int n = wc * 32 + (2 * p + (g >> 1)) * 8 + l7;
#pragma unroll
        for (int k16i = 0; k16i < 4; k16i++) {
            int c = (2 * k16i + (g & 1)) ^ (n & 7);
            lmb[p][k16i] = sb + (uint32_t)(n * 128 + c * 16);
        }
    }

    float acc[2][4][4];          // fp32 master accumulators
    uint32_t facc[2][4][2];      // fp16 window accumulators
#pragma unroll
    for (int ma = 0; ma < 2; ma++)
#pragma unroll
        for (int na = 0; na < 4; na++) {
#pragma unroll
            for (int e = 0; e < 4; e++) acc[ma][na][e] = 0.f;
            facc[ma][na][0] = 0u; facc[ma][na][1] = 0u;
        }

    // staging task executor: load 16 fp32, convert, store 2 swizzled uint4
    auto run_task = [&](int tsk, int jnext, uint32_t abuf) {
        const float* p = x + sgoff[tsk] + jnext * TOK_F;
        float4 f0 = *(const float4*)(p);
        float4 f1 = *(const float4*)(p + 4);
        float4 f2 = *(const float4*)(p + 8);
        float4 f3 = *(const float4*)(p + 12);
        __half2 h;
        uint4 u1, u2;
        h = __floats2half2_rn(f0.x, f0.y); u1.x = *(uint32_t*)&h;
        h = __floats2half2_rn(f0.z, f0.w); u1.y = *(uint32_t*)&h;
        h = __floats2half2_rn(f1.x, f1.y); u1.z = *(uint32_t*)&h;
        h = __floats2half2_rn(f1.z, f1.w); u1.w = *(uint32_t*)&h;
        h = __floats2half2_rn(f2.x, f2.y); u2.x = *(uint32_t*)&h;
        h = __floats2half2_rn(f2.z, f2.w); u2.y = *(uint32_t*)&h;
        h = __floats2half2_rn(f3.x, f3.y); u2.z = *(uint32_t*)&h;
        h = __floats2half2_rn(f3.z, f3.w); u2.w = *(uint32_t*)&h;
        uint32_t a1 = abuf + sadr[tsk];
        *(uint4*)(smem + a1) = u1;
        *(uint4*)(smem + (a1 ^ 16)) = u2;
    };

    // one K-64 substep of MMAs
    auto run_sub = [&](uint32_t aoff, uint32_t bbuf, int hi) {
#pragma unroll
        for (int k16i = 0; k16i < 4; k16i++) {
            uint32_t adel = aoff + (hi ? (uint32_t)hidelta[k16i] : 0u);
            uint32_t a0[4], a1[4], b0[4], b1[4];
            LDMATRIX_X4(a0[0], a0[1], a0[2], a0[3], lma[0][k16i] + adel);
            LDMATRIX_X4(a1[0], a1[1], a1[2], a1[3], lma[1][k16i] + adel);
            LDMATRIX_X4(b0[0], b0[1], b0[2], b0[3], lmb[0][k16i] + bbuf);
            LDMATRIX_X4(b1[0], b1[1], b1[2], b1[3], lmb[1][k16i] + bbuf);
            MMAF16(facc[0][0], a0[0], a0[1], a0[2], a0[3], b0[0], b0[1]);
            MMAF16(facc[0][1], a0[0], a0[1], a0[2], a0[3], b0[2], b0[3]);
            MMAF16(facc[0][2], a0[0], a0[1], a0[2], a0[3], b1[0], b1[1]);
            MMAF16(facc[0][3], a0[0], a0[1], a0[2], a0[3], b1[2], b1[3]);
            MMAF16(facc[1][0], a1[0], a1[1], a1[2], a1[3], b0[0], b0[1]);
            MMAF16(facc[1][1], a1[0], a1[1], a1[2], a1[3], b0[2], b0[3]);
            MMAF16(facc[1][2], a1[0], a1[1], a1[2], a1[3], b1[0], b1[1]);
            MMAF16(facc[1][3], a1[0], a1[1], a1[2], a1[3], b1[2], b1[3]);
        }
    };

    // ---- prologue: B substeps 0,1; A superstep 0 -> slot 0 ----
#pragma unroll
    for (int i = 0; i < 4; i++) CP_ASYNC16(bdst[i], bsrc0 + koff_of(0) + i * 8);
    CP_COMMIT();
#pragma unroll
    for (int i = 0; i < 4; i++) CP_ASYNC16(bdst[i] + B_BYTES, bsrc0 + koff_of(1) + i * 8);
    CP_COMMIT();
    run_task(0, 0, 0);
    run_task(1, 0, 0);
    if (ntask3) run_task(2, 0, 0);

#pragma unroll 1
    for (int u = 0; u < NSUB; u += 2) {
        CP_WAITALL();
        __syncthreads();

        // issue B for substeps u+2, u+3 into slots (u+2)&3, (u+3)&3 (R9 algebra)
        if (u + 2 < NSUB) {
            const int ko = koff_of(u + 2);
#pragma unroll
            for (int i = 0; i < 4; i++)
                CP_ASYNC16(bdst[i] + ((u + 2) & 3) * B_BYTES, bsrc0 + ko + i * 8);
            CP_COMMIT();
        }
        if (u + 3 < NSUB) {
            const int ko = koff_of(u + 3);
#pragma unroll
            for (int i = 0; i < 4; i++)
                CP_ASYNC16(bdst[i] + ((u + 3) & 3) * B_BYTES, bsrc0 + ko + i * 8);
            CP_COMMIT();
        }

        const int T = u >> 2;
        const int pair = (u >> 1) & 1;
        const uint32_t abuf  = (uint32_t)((T & 1) * A_SLOT);

        // stage A for superstep T+1 (slot (T+1)&1): readers were superstep T-1,
        // done before the barrier at u=4T. pair0 -> tasks 0,2; pair1 -> task 1.
        if (T + 1 < 16) {
            const uint32_t abn = (uint32_t)(((T + 1) & 1) * A_SLOT);
            if (pair == 0) {
                run_task(0, T + 1, abn);
                if (ntask3) run_task(2, T + 1, abn);
            } else {
                run_task(1, T + 1, abn);
            }
        }

        // two substeps: u, u+1
        {
            int sub = u & 3;
            run_sub(abuf + (uint32_t)((sub & 1) * 8704), (uint32_t)((u & 3) * B_BYTES),
                    sub >> 1);
            sub = (u + 1) & 3;
            run_sub(abuf + (uint32_t)((sub & 1) * 8704), (uint32_t)(((u + 1) & 3) * B_BYTES),
                    sub >> 1);
        }

        // flush fp16 window into fp32 (window = 2 substeps = 128 K-halves)
#pragma unroll
        for (int ma = 0; ma < 2; ma++)
#pragma unroll
            for (int na = 0; na < 4; na++) {
                float2 f0 = __half22float2(*reinterpret_cast<__half2*>(&facc[ma][na][0]));
                float2 f1 = __half22float2(*reinterpret_cast<__half2*>(&facc[ma][na][1]));
                acc[ma][na][0] += f0.x; acc[ma][na][1] += f0.y;
                acc[ma][na][2] += f1.x; acc[ma][na][3] += f1.y;
                facc[ma][na][0] = 0u; facc[ma][na][1] = 0u;
            }
    }

    // ---- epilogue (mask rows beyond this tile's valid blocks) ----
    const int l4 = lid >> 2, lc = lid & 3;
#pragma unroll
    for (int ma = 0; ma < 2; ma++) {
        int rl = wr * 32 + ma * 16 + l4;
#pragma unroll
        for (int na = 0; na < 4; na++) {
            int col = wc * 32 + na * 8 + lc * 2;
            if (rl < nrow)
                *(float2*)(outp + (size_t)(o0 * 4 + rl) * 128 + col) =
                    make_float2(acc[ma][na][0], acc[ma][na][1]);
            if (rl + 8 < nrow)
                *(float2*)(outp + (size_t)(o0 * 4 + rl + 8) * 128 + col) =
                    make_float2(acc[ma][na][2], acc[ma][na][3]);
        }
    }
}

// ---------------- launch ----------------
extern "C" void kernel_launch(void* const* d_in, const int* in_sizes, int n_in,
                              void* d_out, int out_size) {
    const float* k  = (const float*)d_in[0];
    const float* v  = (const float*)d_in[1];
    const float* wk = (const float*)d_in[2];
    const float* wv = (const float*)d_in[3];
    const int*   cu = (const int*)d_in[4];
    int nseq = in_sizes[4] - 1;
    int total_tokens = in_sizes[0] / (N_HEADS * H_DIM);

    prep_kernel<<<1025, dim3(32, 8)>>>(cu, nseq, wk, wv, (float*)d_out);

    int ntiles_ub = total_tokens / 256 + MAXSEQ + 1;
    cudaFuncSetAttribute(gemm_kernel, cudaFuncAttributeMaxDynamicSharedMemorySize, SMEM_GEMM);
    gemm_kernel<<<dim3(ntiles_ub, 2), 256, SMEM_GEMM>>>(k, v, (float*)d_out);
}

// round 13
// speedup vs baseline: 1.9910x; 1.2805x over previous
#include <cuda_runtime.h>
#include <cuda_fp16.h>
#include <cstdint>

#define N_HEADS 4
#define H_DIM   128
#define TOK_F   512
#define K_DIM   4096
#define BLK     32
#define STRIDE  16
#define MAXSEQ  256
#define MAXTILE 8192

#define A_SLOT  17408           // 2(dh) x 68 rows x 128B
#define TOK_OFF (2 * A_SLOT)
#define SMEM_GEMM (TOK_OFF + 128)

// ---------------- device scratch ----------------
__device__ int    g_total_out;
__device__ int    g_ntiles;
__device__ int    g_tile_o0[MAXTILE];
__device__ int    g_tile_tok0[MAXTILE];
__device__ int    g_tile_lim[MAXTILE];
__device__ int    g_tile_nrow[MAXTILE];
// B in MMA fragment order: [mat][(atom*256 + chunk)*32 + lane] = {b0,b1}
__device__ uint2  g_wB[2][131072];

static __device__ __forceinline__ uint32_t smem_u32(const void* p) {
    uint32_t a;
    asm("{ .reg .u64 t; cvta.to.shared.u64 t, %1; cvt.u32.u64 %0, t; }" : "=r"(a) : "l"(p));
    return a;
}

#define LDMATRIX_X4(r0, r1, r2, r3, addr) \
    asm volatile("ldmatrix.sync.aligned.m8n8.x4.shared.b16 {%0,%1,%2,%3}, [%4];" \
                 : "=r"(r0), "=r"(r1), "=r"(r2), "=r"(r3) : "r"(addr))

// fp16-accumulate MMA: D,C packed half2 x2
#define MMAF16(c, a0, a1, a2, a3, b0, b1) \
    asm volatile("mma.sync.aligned.m16n8k16.row.col.f16.f16.f16.f16 " \
                 "{%0,%1}, {%2,%3,%4,%5}, {%6,%7}, {%0,%1};" \
                 : "+r"((c)[0]), "+r"((c)[1]) \
                 : "r"(a0), "r"(a1), "r"(a2), "r"(a3), "r"(b0), "r"(b1))

// substep u -> base k16 chunk: j = T + 16*(sub>>1), dh = sub&1
static __device__ __forceinline__ int cb_of(int u) {
    return (u >> 2) * 8 + ((u & 2) << 6) + (u & 1) * 4;
}

// ---------------- kernel 1: prep = metadata/tile-table + W fragment pack ----------------
__global__ void prep_kernel(const int* __restrict__ cu, int nseq,
                            const float* __restrict__ wk, const float* __restrict__ wv,
                            float* __restrict__ dout) {
    int t = threadIdx.y * 32 + threadIdx.x;
    if (blockIdx.x == 1024) {
        __shared__ int s_ol[MAXSEQ];
        __shared__ int s_cu[MAXSEQ + 1];
        __shared__ int s_ts[MAXSEQ + 1];
        if (t < nseq) {
            int n = cu[t + 1] - cu[t];
            s_ol[t] = (n >= BLK) ? (n - BLK) / STRIDE : 0;
        }
        __syncthreads();
        if (t == 0) {
            int acc = 0, tacc = 0;
            s_cu[0] = 0; s_ts[0] = 0;
            for (int b = 0; b < nseq; b++) {
                acc += s_ol[b];
                tacc += (s_ol[b] + 15) >> 4;
                s_cu[b + 1] = acc;
                s_ts[b + 1] = tacc;
            }
            g_total_out = acc;
            g_ntiles = tacc;
        }
        __syncthreads();
        int total = s_cu[nseq];
        int ntl = s_ts[nseq];
        for (int i = t; i <= nseq; i += 256)
            dout[(size_t)2 * total * 512 + i] = (float)s_cu[i];
        for (int x = t; x < ntl; x += 256) {
            int b = 0;
            while (s_ts[b + 1] <= x) b++;
            int ti = x - s_ts[b];
            int o0 = s_cu[b] + ti * 16;
            int ol = s_cu[b + 1] - o0;
            g_tile_o0[x]   = o0;
            g_tile_tok0[x] = cu[b] + ti * 256;
            g_tile_lim[x]  = cu[b + 1] - 16;
            g_tile_nrow[x] = (ol < 16 ? ol : 16) * 4;
        }
        return;
    }
    // fragment-pack W: idx -> (atom a, chunk c, lane l)
    int z   = blockIdx.x >> 9;
    int rem = blockIdx.x & 511;
    const float* w = z ? wv : wk;
    int idx = rem * 256 + t;                  // 0..131071
    int a = idx >> 13;
    int c = (idx >> 5) & 255;
    int l = idx & 31;
    int n  = 8 * a + (l >> 2);
    int k1 = 16 * c + 2 * (l & 3);
    float v0 = w[(size_t)k1 * H_DIM + n];
    float v1 = w[(size_t)(k1 + 1) * H_DIM + n];
    float v2 = w[(size_t)(k1 + 8) * H_DIM + n];
    float v3 = w[(size_t)(k1 + 9) * H_DIM + n];
    __half2 h0 = __floats2half2_rn(v0, v1);
    __half2 h1 = __floats2half2_rn(v2, v3);
    uint2 u;
    u.x = *reinterpret_cast<uint32_t*>(&h0);
    u.y = *reinterpret_cast<uint32_t*>(&h1);
    g_wB[z][idx] = u;
}

// ---------------- kernel 2: HMMA GEMM, B direct-from-L2 in fragment order ----------------
// 256 thr = 8 warps in 2(M) x 4(N); warp tile 32x32; CTA tile 64x128.
// A: token-dedup smem staging (17 tokens per superstep of 4 K-64 substeps),
//    ONE __syncthreads per superstep. B: LDG.64 fragments, prefetched 1 substep ahead.
__global__ __launch_bounds__(256, 2)
void gemm_kernel(const float* __restrict__ kin, const float* __restrict__ vin,
                 float* __restrict__ dout) {
    extern __shared__ __align__(128) char smem[];
    const uint32_t sa = smem_u32(smem);            // A: 2 slots x 17408
    int* s_tok = (int*)(smem + TOK_OFF);

    const int tid = threadIdx.x;
    const int wid = tid >> 5;
    const int lid = tid & 31;
    const int bx  = blockIdx.x;
    if (bx >= g_ntiles) return;
    const int total_out = g_total_out;
    const int o0   = g_tile_o0[bx];
    const int tok0 = g_tile_tok0[bx];
    const int lim  = g_tile_lim[bx];
    const int nrow = g_tile_nrow[bx];

    const int mat = blockIdx.y;
    const float* __restrict__ x = mat ? vin : kin;
    const uint2* __restrict__ wB = g_wB[mat];
    float* __restrict__ outp = dout + (size_t)mat * (size_t)total_out * 512;

    if (tid < 17) {
        int tk = tok0 + 16 * tid;
        s_tok[tid] = tk < lim ? tk : lim;
    }
    __syncthreads();

    // ---- A staging tasks (R12 verified): tau = sr*8 + dh*4 + cpair ----
    int      sgoff[3];
    uint32_t sadr[3];
    const int ntask3 = (tid < 32) ? 1 : 0;
#pragma unroll
    for (int tsk = 0; tsk < 3; tsk++) {
        int tau = tsk * 256 + tid;
        if (tau >= 544) tau = 543;
        int sr = tau >> 3, dh = (tau >> 2) & 1, cp = tau & 3;
        int i = sr >> 2, h = sr & 3;
        sgoff[tsk] = s_tok[i] * TOK_F + h * H_DIM + dh * 64 + cp * 16;
        sadr[tsk]  = (uint32_t)(dh * 8704 + sr * 128 + (((2 * cp) ^ (sr & 7)) * 16));
    }

    // ---- ldmatrix A addresses (R12 verified) ----
    const int wr = wid >> 2;       // M position 0..1
    const int wc = wid & 3;        // N position 0..3
    const int g  = lid >> 3;
    const int l7 = lid & 7;
    uint32_t lma[2][4];
    int hidelta[4];
#pragma unroll
    for (int k16i = 0; k16i < 4; k16i++) {
        int c = 2 * k16i + (g >> 1);
        hidelta[k16i] = 512 + (((c ^ l7) & 4) ? -64 : 64);
#pragma unroll
        for (int ma = 0; ma < 2; ma++) {
            int sr = wr * 32 + ma * 16 + (g & 1) * 8 + l7;
            lma[ma][k16i] = sa + (uint32_t)(sr * 128 + ((c ^ (sr & 7)) * 16));
        }
    }

    // ---- B fragment element bases: atom a = wc*4 + p ----
    int bbase[4];
#pragma unroll
    for (int p = 0; p < 4; p++)
        bbase[p] = ((wc * 4 + p) << 13) + lid;

    float acc[2][4][4];
    uint32_t facc[2][4][2];
#pragma unroll
    for (int ma = 0; ma < 2; ma++)
#pragma unroll
        for (int na = 0; na < 4; na++) {
#pragma unroll
            for (int e = 0; e < 4; e++) acc[ma][na][e] = 0.f;
            facc[ma][na][0] = 0u; facc[ma][na][1] = 0u;
        }

    // staging task: 16 fp32 LDG -> cvt -> 2 swizzled uint4 STS
    auto run_task = [&](int tsk, int jnext, uint32_t abuf) {
        const float* p = x + sgoff[tsk] + jnext * TOK_F;
        float4 f0 = *(const float4*)(p);
        float4 f1 = *(const float4*)(p + 4);
        float4 f2 = *(const float4*)(p + 8);
        float4 f3 = *(const float4*)(p + 12);
        __half2 h;
        uint4 u1, u2;
        h = __floats2half2_rn(f0.x, f0.y); u1.x = *(uint32_t*)&h;
        h = __floats2half2_rn(f0.z, f0.w); u1.y = *(uint32_t*)&h;
        h = __floats2half2_rn(f1.x, f1.y); u1.z = *(uint32_t*)&h;
        h = __floats2half2_rn(f1.z, f1.w); u1.w = *(uint32_t*)&h;
        h = __floats2half2_rn(f2.x, f2.y); u2.x = *(uint32_t*)&h;
        h = __floats2half2_rn(f2.z, f2.w); u2.y = *(uint32_t*)&h;
        h = __floats2half2_rn(f3.x, f3.y); u2.z = *(uint32_t*)&h;
        h = __floats2half2_rn(f3.z, f3.w); u2.w = *(uint32_t*)&h;
        uint32_t a1 = abuf + sadr[tsk];
        *(uint4*)(smem + a1) = u1;
        *(uint4*)(smem + (a1 ^ 16)) = u2;
    };

    // ---- prologue: stage A superstep 0; preload B fragments for substep 0 ----
    run_task(0, 0, 0);
    run_task(1, 0, 0);
    if (ntask3) run_task(2, 0, 0);

    uint2 bb[16];                              // current substep fragments
    {
        const int cb0 = cb_of(0);
#pragma unroll
        for (int k16i = 0; k16i < 4; k16i++)
#pragma unroll
            for (int p = 0; p < 4; p++)
                bb[k16i * 4 + p] = wB[bbase[p] + (cb0 + k16i) * 32];
    }

#pragma unroll 1
    for (int T = 0; T < 16; T++) {
        __syncthreads();   // publish A slot T&1; slot (T+1)&1 free (readers were T-1)
        const uint32_t ab  = (uint32_t)((T & 1) * A_SLOT);
        const uint32_t abn = (uint32_t)(((T + 1) & 1) * A_SLOT);
        const int stage_ok = (T + 1 < 16);

#pragma unroll
        for (int sub = 0; sub < 4; sub++) {
            const int u = T * 4 + sub;
            const int unext = (u + 1 < 64) ? u + 1 : u;
            const int cbn = cb_of(unext);
            const uint32_t adh = ab + (uint32_t)((sub & 1) * 8704);
            const int hi = sub >> 1;

#pragma unroll
            for (int k16i = 0; k16i < 4; k16i++) {
                uint32_t adel = adh + (hi ? (uint32_t)hidelta[k16i] : 0u);
                uint32_t a0[4], a1[4];
                LDMATRIX_X4(a0[0], a0[1], a0[2], a0[3], lma[0][k16i] + adel);
                LDMATRIX_X4(a1[0], a1[1], a1[2], a1[3], lma[1][k16i] + adel);
                MMAF16(facc[0][0], a0[0], a0[1], a0[2], a0[3], bb[k16i*4+0].x, bb[k16i*4+0].y);
                MMAF16(facc[0][1], a0[0], a0[1], a0[2], a0[3], bb[k16i*4+1].x, bb[k16i*4+1].y);
                MMAF16(facc[0][2], a0[0], a0[1], a0[2], a0[3], bb[k16i*4+2].x, bb[k16i*4+2].y);
                MMAF16(facc[0][3], a0[0], a0[1], a0[2], a0[3], bb[k16i*4+3].x, bb[k16i*4+3].y);
                MMAF16(facc[1][0], a1[0], a1[1], a1[2], a1[3], bb[k16i*4+0].x, bb[k16i*4+0].y);
                MMAF16(facc[1][1], a1[0], a1[1], a1[2], a1[3], bb[k16i*4+1].x, bb[k16i*4+1].y);
                MMAF16(facc[1][2], a1[0], a1[1], a1[2], a1[3], bb[k16i*4+2].x, bb[k16i*4+2].y);
                MMAF16(facc[1][3], a1[0], a1[1], a1[2], a1[3], bb[k16i*4+3].x, bb[k16i*4+3].y);
                // prefetch next substep's fragments into the same slots
#pragma unroll
                for (int p = 0; p < 4; p++)
                    bb[k16i * 4 + p] = wB[bbase[p] + (cbn + k16i) * 32];
            }

            // stage A for superstep T+1 spread across subs 0..2
            if (stage_ok) {
                if (sub == 0) run_task(0, T + 1, abn);
                else if (sub == 1) run_task(1, T + 1, abn);
                else if (sub == 2) { if (ntask3) run_task(2, T + 1, abn); }
            }

            // flush fp16 window every 2 substeps
            if (sub & 1) {
#pragma unroll
                for (int ma = 0; ma < 2; ma++)
#pragma unroll
                    for (int na = 0; na < 4; na++) {
                        float2 f0 = __half22float2(*reinterpret_cast<__half2*>(&facc[ma][na][0]));
                        float2 f1 = __half22float2(*reinterpret_cast<__half2*>(&facc[ma][na][1]));
                        acc[ma][na][0] += f0.x; acc[ma][na][1] += f0.y;
                        acc[ma][na][2] += f1.x; acc[ma][na][3] += f1.y;
                        facc[ma][na][0] = 0u; facc[ma][na][1] = 0u;
                    }
            }
        }
    }

    // ---- epilogue (mask rows beyond this tile's valid blocks) ----
    const int l4 = lid >> 2, lc = lid & 3;
#pragma unroll
    for (int ma = 0; ma < 2; ma++) {
        int rl = wr * 32 + ma * 16 + l4;
#pragma unroll
        for (int na = 0; na < 4; na++) {
            int col = wc * 32 + na * 8 + lc * 2;
            if (rl < nrow)
                *(float2*)(outp + (size_t)(o0 * 4 + rl) * 128 + col) =
                    make_float2(acc[ma][na][0], acc[ma][na][1]);
            if (rl + 8 < nrow)
                *(float2*)(outp + (size_t)(o0 * 4 + rl + 8) * 128 + col) =
                    make_float2(acc[ma][na][2], acc[ma][na][3]);
        }
    }
}

// ---------------- launch ----------------
extern "C" void kernel_launch(void* const* d_in, const int* in_sizes, int n_in,
                              void* d_out, int out_size) {
    const float* k  = (const float*)d_in[0];
    const float* v  = (const float*)d_in[1];
    const float* wk = (const float*)d_in[2];
    const float* wv = (const float*)d_in[3];
    const int*   cu = (const int*)d_in[4];
    int nseq = in_sizes[4] - 1;
    int total_tokens = in_sizes[0] / (N_HEADS * H_DIM);

    prep_kernel<<<1025, dim3(32, 8)>>>(cu, nseq, wk, wv, (float*)d_out);

    int ntiles_ub = total_tokens / 256 + MAXSEQ + 1;
    cudaFuncSetAttribute(gemm_kernel, cudaFuncAttributeMaxDynamicSharedMemorySize, SMEM_GEMM);
    gemm_kernel<<<dim3(ntiles_ub, 2), 256, SMEM_GEMM>>>(k, v, (float*)d_out);
}